// round 2
// baseline (speedup 1.0000x reference)
#include <cuda_runtime.h>

#define N_NODES 100000
#define N_EDGES 1600000
#define IN_DIM  128
#define HID     64
#define OUT_DIM 64
#define EPS     0.1f

// ---------------- scratch (static device globals; no runtime alloc) --------
__device__ float g_h[N_NODES * HID];      // node features, updated in place
__device__ float g_agg[N_NODES * HID];    // SpMM accumulator
__device__ int   g_cnt[N_NODES];          // edge in-degree counts
__device__ float g_dinv[N_NODES];         // deg^{-1/2}

// packed per-edge record: {src, dst, norm, pad} -> one 16B load per edge
struct __align__(16) Edge { int src; int dst; float norm; float pad; };
__device__ Edge g_edge[N_EDGES];

// ---------------- init: zero agg + cnt -------------------------------------
__global__ void k_init() {
    int t = blockIdx.x * blockDim.x + threadIdx.x;
    if (t < N_NODES * (HID / 4))
        reinterpret_cast<float4*>(g_agg)[t] = make_float4(0.f, 0.f, 0.f, 0.f);
    if (t < N_NODES)
        g_cnt[t] = 0;
}

// ---------------- embed: h = x @ emb_w + emb_b ------------------------------
__global__ void __launch_bounds__(256) k_embed(const float* __restrict__ x,
                                               const float* __restrict__ w,
                                               const float* __restrict__ b) {
    __shared__ float Ws[IN_DIM * HID];   // 32 KB
    __shared__ float Bs[HID];
    for (int i = threadIdx.x; i < IN_DIM * HID / 4; i += blockDim.x)
        reinterpret_cast<float4*>(Ws)[i] = reinterpret_cast<const float4*>(w)[i];
    if (threadIdx.x < HID) Bs[threadIdx.x] = b[threadIdx.x];
    __syncthreads();

    int node = blockIdx.x * blockDim.x + threadIdx.x;
    if (node >= N_NODES) return;

    float acc[HID];
#pragma unroll
    for (int j = 0; j < HID; j++) acc[j] = Bs[j];

    const float4* xr = reinterpret_cast<const float4*>(x + (size_t)node * IN_DIM);
#pragma unroll 4
    for (int k4 = 0; k4 < IN_DIM / 4; k4++) {
        float4 xv = xr[k4];
        float xk[4] = {xv.x, xv.y, xv.z, xv.w};
#pragma unroll
        for (int kk = 0; kk < 4; kk++) {
            const float4* wrow = reinterpret_cast<const float4*>(Ws + (k4 * 4 + kk) * HID);
#pragma unroll
            for (int j4 = 0; j4 < HID / 4; j4++) {
                float4 wv = wrow[j4];
                acc[j4 * 4 + 0] += xk[kk] * wv.x;
                acc[j4 * 4 + 1] += xk[kk] * wv.y;
                acc[j4 * 4 + 2] += xk[kk] * wv.z;
                acc[j4 * 4 + 3] += xk[kk] * wv.w;
            }
        }
    }

    float4* hout = reinterpret_cast<float4*>(g_h + (size_t)node * HID);
#pragma unroll
    for (int j4 = 0; j4 < HID / 4; j4++)
        hout[j4] = make_float4(acc[j4 * 4 + 0], acc[j4 * 4 + 1],
                               acc[j4 * 4 + 2], acc[j4 * 4 + 3]);
}

// ---------------- degree count ----------------------------------------------
__global__ void k_deg(const int* __restrict__ ei) {
    int e = blockIdx.x * blockDim.x + threadIdx.x;
    if (e >= N_EDGES) return;
    atomicAdd(&g_cnt[ei[N_EDGES + e]], 1);
}

// ---------------- dinv = rsqrt(cnt + 2) (self-loop weight 2.0) --------------
__global__ void k_dinv() {
    int i = blockIdx.x * blockDim.x + threadIdx.x;
    if (i >= N_NODES) return;
    g_dinv[i] = rsqrtf((float)g_cnt[i] + 2.0f);
}

// ---------------- build packed edge records ---------------------------------
__global__ void k_norm(const int* __restrict__ ei) {
    int e = blockIdx.x * blockDim.x + threadIdx.x;
    if (e >= N_EDGES) return;
    int src = ei[e];
    int dst = ei[N_EDGES + e];
    Edge rec;
    rec.src = src;
    rec.dst = dst;
    rec.norm = g_dinv[src] * g_dinv[dst];
    rec.pad = 0.f;
    g_edge[e] = rec;
}

// ---------------- SpMM scatter: agg[dst] += norm * h[src] -------------------
// 16 threads per edge, each handles one float4 (64 floats per row)
__global__ void __launch_bounds__(256) k_scatter() {
    long long t = (long long)blockIdx.x * blockDim.x + threadIdx.x;
    int e = (int)(t >> 4);
    int c = ((int)t & 15) << 2;
    if (e >= N_EDGES) return;
    Edge rec = g_edge[e];                 // one LDG.128, broadcast across 16 lanes
    float wgt = rec.norm;
    float4 v = *reinterpret_cast<const float4*>(g_h + (size_t)rec.src * HID + c);
    float* p = g_agg + (size_t)rec.dst * HID + c;
#if __CUDA_ARCH__ >= 900
    asm volatile("red.global.add.v4.f32 [%0], {%1, %2, %3, %4};"
                 :: "l"(p), "f"(v.x * wgt), "f"(v.y * wgt),
                    "f"(v.z * wgt), "f"(v.w * wgt)
                 : "memory");
#else
    atomicAdd(p + 0, v.x * wgt);
    atomicAdd(p + 1, v.y * wgt);
    atomicAdd(p + 2, v.z * wgt);
    atomicAdd(p + 3, v.w * wgt);
#endif
}

// ---------------- update: h -= eps*(agg + 2*dinv^2*h); agg := 0 -------------
__global__ void k_update() {
    int t = blockIdx.x * blockDim.x + threadIdx.x;
    if (t >= N_NODES * (HID / 4)) return;
    int i = t >> 4;
    float di = g_dinv[i];
    float sw = 2.0f * di * di;          // self-loop norm
    float4 hv = reinterpret_cast<float4*>(g_h)[t];
    float4 av = reinterpret_cast<float4*>(g_agg)[t];
    hv.x -= EPS * (av.x + sw * hv.x);
    hv.y -= EPS * (av.y + sw * hv.y);
    hv.z -= EPS * (av.z + sw * hv.z);
    hv.w -= EPS * (av.w + sw * hv.w);
    reinterpret_cast<float4*>(g_h)[t] = hv;
    reinterpret_cast<float4*>(g_agg)[t] = make_float4(0.f, 0.f, 0.f, 0.f); // rezero for next iter
}

// ---------------- readout: out = tanh(h) @ ro_w + ro_b ----------------------
__global__ void __launch_bounds__(256) k_readout(const float* __restrict__ w,
                                                 const float* __restrict__ b,
                                                 float* __restrict__ out) {
    __shared__ float Ws[HID * OUT_DIM];  // 16 KB
    __shared__ float Bs[OUT_DIM];
    for (int i = threadIdx.x; i < HID * OUT_DIM / 4; i += blockDim.x)
        reinterpret_cast<float4*>(Ws)[i] = reinterpret_cast<const float4*>(w)[i];
    if (threadIdx.x < OUT_DIM) Bs[threadIdx.x] = b[threadIdx.x];
    __syncthreads();

    int node = blockIdx.x * blockDim.x + threadIdx.x;
    if (node >= N_NODES) return;

    float acc[OUT_DIM];
#pragma unroll
    for (int j = 0; j < OUT_DIM; j++) acc[j] = Bs[j];

    const float4* hr = reinterpret_cast<const float4*>(g_h + (size_t)node * HID);
#pragma unroll 4
    for (int k4 = 0; k4 < HID / 4; k4++) {
        float4 hv = hr[k4];
        float hk[4] = {tanhf(hv.x), tanhf(hv.y), tanhf(hv.z), tanhf(hv.w)};
#pragma unroll
        for (int kk = 0; kk < 4; kk++) {
            const float4* wrow = reinterpret_cast<const float4*>(Ws + (k4 * 4 + kk) * OUT_DIM);
#pragma unroll
            for (int j4 = 0; j4 < OUT_DIM / 4; j4++) {
                float4 wv = wrow[j4];
                acc[j4 * 4 + 0] += hk[kk] * wv.x;
                acc[j4 * 4 + 1] += hk[kk] * wv.y;
                acc[j4 * 4 + 2] += hk[kk] * wv.z;
                acc[j4 * 4 + 3] += hk[kk] * wv.w;
            }
        }
    }

    float4* orow = reinterpret_cast<float4*>(out + (size_t)node * OUT_DIM);
#pragma unroll
    for (int j4 = 0; j4 < OUT_DIM / 4; j4++)
        orow[j4] = make_float4(acc[j4 * 4 + 0], acc[j4 * 4 + 1],
                               acc[j4 * 4 + 2], acc[j4 * 4 + 3]);
}

// ---------------- launch ----------------------------------------------------
extern "C" void kernel_launch(void* const* d_in, const int* in_sizes, int n_in,
                              void* d_out, int out_size) {
    const float* x     = (const float*)d_in[0];
    const int*   ei    = (const int*)d_in[1];
    const float* emb_w = (const float*)d_in[2];
    const float* emb_b = (const float*)d_in[3];
    const float* ro_w  = (const float*)d_in[4];
    const float* ro_b  = (const float*)d_in[5];
    float* out = (float*)d_out;

    const int T = 256;
    int blk_agg   = (N_NODES * (HID / 4) + T - 1) / T;  // 6250
    int blk_node  = (N_NODES + T - 1) / T;              // 391
    int blk_edge  = (N_EDGES + T - 1) / T;              // 6250
    long long scatter_threads = (long long)N_EDGES * 16;
    int blk_scat  = (int)((scatter_threads + T - 1) / T);

    k_init<<<blk_agg, T>>>();
    k_embed<<<blk_node, T>>>(x, emb_w, emb_b);
    k_deg<<<blk_edge, T>>>(ei);
    k_dinv<<<blk_node, T>>>();
    k_norm<<<blk_edge, T>>>(ei);

    for (int it = 0; it < 4; it++) {
        k_scatter<<<blk_scat, T>>>();
        k_update<<<blk_agg, T>>>();
    }

    k_readout<<<blk_node, T>>>(ro_w, ro_b, out);
    (void)in_sizes; (void)n_in; (void)out_size;
}

// round 3
// speedup vs baseline: 1.7253x; 1.7253x over previous
#include <cuda_runtime.h>

#define N_NODES 100000
#define N_EDGES 1600000
#define IN_DIM  128
#define HID     64
#define OUT_DIM 64
#define EPS     0.1f
#define NBLK    ((N_NODES + 255) / 256)   // 391 scan blocks

// ---------------- scratch (static device globals; no runtime alloc) --------
__device__ float g_hA[N_NODES * HID];
__device__ float g_hB[N_NODES * HID];
__device__ int   g_cnt[N_NODES];          // in-degree
__device__ int   g_off[N_NODES];          // CSR row offsets (exclusive scan)
__device__ int   g_fill[N_NODES];         // fill cursors
__device__ int   g_bsum[NBLK];            // per-block scan sums
__device__ int   g_bpre[NBLK];            // scanned block sums
__device__ float g_dinv[N_NODES];         // (deg+2)^{-1/2}
__device__ int2  g_csr[N_EDGES];          // {src, norm-as-int} sorted by dst

// ---------------- init ------------------------------------------------------
__global__ void k_init() {
    int i = blockIdx.x * blockDim.x + threadIdx.x;
    if (i < N_NODES) { g_cnt[i] = 0; g_fill[i] = 0; }
}

// ---------------- embed: hA = x @ emb_w + emb_b -----------------------------
__global__ void __launch_bounds__(256) k_embed(const float* __restrict__ x,
                                               const float* __restrict__ w,
                                               const float* __restrict__ b) {
    __shared__ float Ws[IN_DIM * HID];   // 32 KB
    __shared__ float Bs[HID];
    for (int i = threadIdx.x; i < IN_DIM * HID / 4; i += blockDim.x)
        reinterpret_cast<float4*>(Ws)[i] = reinterpret_cast<const float4*>(w)[i];
    if (threadIdx.x < HID) Bs[threadIdx.x] = b[threadIdx.x];
    __syncthreads();

    int node = blockIdx.x * blockDim.x + threadIdx.x;
    if (node >= N_NODES) return;

    float acc[HID];
#pragma unroll
    for (int j = 0; j < HID; j++) acc[j] = Bs[j];

    const float4* xr = reinterpret_cast<const float4*>(x + (size_t)node * IN_DIM);
#pragma unroll 4
    for (int k4 = 0; k4 < IN_DIM / 4; k4++) {
        float4 xv = xr[k4];
        float xk[4] = {xv.x, xv.y, xv.z, xv.w};
#pragma unroll
        for (int kk = 0; kk < 4; kk++) {
            const float4* wrow = reinterpret_cast<const float4*>(Ws + (k4 * 4 + kk) * HID);
#pragma unroll
            for (int j4 = 0; j4 < HID / 4; j4++) {
                float4 wv = wrow[j4];
                acc[j4 * 4 + 0] += xk[kk] * wv.x;
                acc[j4 * 4 + 1] += xk[kk] * wv.y;
                acc[j4 * 4 + 2] += xk[kk] * wv.z;
                acc[j4 * 4 + 3] += xk[kk] * wv.w;
            }
        }
    }

    float4* hout = reinterpret_cast<float4*>(g_hA + (size_t)node * HID);
#pragma unroll
    for (int j4 = 0; j4 < HID / 4; j4++)
        hout[j4] = make_float4(acc[j4 * 4 + 0], acc[j4 * 4 + 1],
                               acc[j4 * 4 + 2], acc[j4 * 4 + 3]);
}

// ---------------- degree count ----------------------------------------------
__global__ void k_deg(const int* __restrict__ ei) {
    int e = blockIdx.x * blockDim.x + threadIdx.x;
    if (e >= N_EDGES) return;
    atomicAdd(&g_cnt[ei[N_EDGES + e]], 1);
}

// ---------------- dinv = rsqrt(cnt + 2) -------------------------------------
__global__ void k_dinv() {
    int i = blockIdx.x * blockDim.x + threadIdx.x;
    if (i >= N_NODES) return;
    g_dinv[i] = rsqrtf((float)g_cnt[i] + 2.0f);
}

// ---------------- 3-phase exclusive scan of g_cnt -> g_off ------------------
__global__ void k_scan_block() {
    __shared__ int s[256];
    int i = blockIdx.x * 256 + threadIdx.x;
    int v = (i < N_NODES) ? g_cnt[i] : 0;
    s[threadIdx.x] = v;
    __syncthreads();
#pragma unroll
    for (int d = 1; d < 256; d <<= 1) {
        int t = (threadIdx.x >= d) ? s[threadIdx.x - d] : 0;
        __syncthreads();
        s[threadIdx.x] += t;
        __syncthreads();
    }
    if (i < N_NODES) g_off[i] = s[threadIdx.x] - v;   // exclusive within block
    if (threadIdx.x == 255) g_bsum[blockIdx.x] = s[255];
}

__global__ void k_scan_top() {
    __shared__ int s[512];
    int tid = threadIdx.x;
    int v = (tid < NBLK) ? g_bsum[tid] : 0;
    s[tid] = v;
    __syncthreads();
#pragma unroll
    for (int d = 1; d < 512; d <<= 1) {
        int t = (tid >= d) ? s[tid - d] : 0;
        __syncthreads();
        s[tid] += t;
        __syncthreads();
    }
    if (tid < NBLK) g_bpre[tid] = s[tid] - v;         // exclusive
}

__global__ void k_scan_add() {
    int i = blockIdx.x * 256 + threadIdx.x;
    if (i < N_NODES) g_off[i] += g_bpre[blockIdx.x];
}

// ---------------- fill CSR ---------------------------------------------------
__global__ void k_fill(const int* __restrict__ ei) {
    int e = blockIdx.x * blockDim.x + threadIdx.x;
    if (e >= N_EDGES) return;
    int src = ei[e];
    int dst = ei[N_EDGES + e];
    int pos = g_off[dst] + atomicAdd(&g_fill[dst], 1);
    g_csr[pos] = make_int2(src, __float_as_int(g_dinv[src] * g_dinv[dst]));
}

// ---------------- gather SpMM + fused update --------------------------------
// hout[i] = hin[i] - EPS*(sum_e norm_e*hin[src_e] + 2*dinv[i]^2*hin[i])
// 16 threads per node; each thread owns one float4 column chunk.
__global__ void __launch_bounds__(256) k_gather(const float* __restrict__ hin,
                                                float* __restrict__ hout) {
    int t = blockIdx.x * blockDim.x + threadIdx.x;
    int node = t >> 4;
    int c = (t & 15) << 2;
    if (node >= N_NODES) return;

    int beg = g_off[node];
    int end = beg + g_cnt[node];

    float4 acc = make_float4(0.f, 0.f, 0.f, 0.f);
    int e = beg;
    // 2-deep unroll for MLP
    for (; e + 1 < end; e += 2) {
        int2 r0 = g_csr[e];
        int2 r1 = g_csr[e + 1];
        float w0 = __int_as_float(r0.y);
        float w1 = __int_as_float(r1.y);
        float4 v0 = *reinterpret_cast<const float4*>(hin + (size_t)r0.x * HID + c);
        float4 v1 = *reinterpret_cast<const float4*>(hin + (size_t)r1.x * HID + c);
        acc.x += w0 * v0.x + w1 * v1.x;
        acc.y += w0 * v0.y + w1 * v1.y;
        acc.z += w0 * v0.z + w1 * v1.z;
        acc.w += w0 * v0.w + w1 * v1.w;
    }
    if (e < end) {
        int2 r0 = g_csr[e];
        float w0 = __int_as_float(r0.y);
        float4 v0 = *reinterpret_cast<const float4*>(hin + (size_t)r0.x * HID + c);
        acc.x += w0 * v0.x;
        acc.y += w0 * v0.y;
        acc.z += w0 * v0.z;
        acc.w += w0 * v0.w;
    }

    float di = g_dinv[node];
    float sw = 2.0f * di * di;
    float4 hv = *reinterpret_cast<const float4*>(hin + (size_t)node * HID + c);
    float4 o;
    o.x = hv.x - EPS * (acc.x + sw * hv.x);
    o.y = hv.y - EPS * (acc.y + sw * hv.y);
    o.z = hv.z - EPS * (acc.z + sw * hv.z);
    o.w = hv.w - EPS * (acc.w + sw * hv.w);
    *reinterpret_cast<float4*>(hout + (size_t)node * HID + c) = o;
}

// ---------------- readout: out = tanh(hA) @ ro_w + ro_b ---------------------
__global__ void __launch_bounds__(256) k_readout(const float* __restrict__ w,
                                                 const float* __restrict__ b,
                                                 float* __restrict__ out) {
    __shared__ float Ws[HID * OUT_DIM];  // 16 KB
    __shared__ float Bs[OUT_DIM];
    for (int i = threadIdx.x; i < HID * OUT_DIM / 4; i += blockDim.x)
        reinterpret_cast<float4*>(Ws)[i] = reinterpret_cast<const float4*>(w)[i];
    if (threadIdx.x < OUT_DIM) Bs[threadIdx.x] = b[threadIdx.x];
    __syncthreads();

    int node = blockIdx.x * blockDim.x + threadIdx.x;
    if (node >= N_NODES) return;

    float acc[OUT_DIM];
#pragma unroll
    for (int j = 0; j < OUT_DIM; j++) acc[j] = Bs[j];

    const float4* hr = reinterpret_cast<const float4*>(g_hA + (size_t)node * HID);
#pragma unroll 4
    for (int k4 = 0; k4 < HID / 4; k4++) {
        float4 hv = hr[k4];
        float hk[4] = {tanhf(hv.x), tanhf(hv.y), tanhf(hv.z), tanhf(hv.w)};
#pragma unroll
        for (int kk = 0; kk < 4; kk++) {
            const float4* wrow = reinterpret_cast<const float4*>(Ws + (k4 * 4 + kk) * OUT_DIM);
#pragma unroll
            for (int j4 = 0; j4 < OUT_DIM / 4; j4++) {
                float4 wv = wrow[j4];
                acc[j4 * 4 + 0] += hk[kk] * wv.x;
                acc[j4 * 4 + 1] += hk[kk] * wv.y;
                acc[j4 * 4 + 2] += hk[kk] * wv.z;
                acc[j4 * 4 + 3] += hk[kk] * wv.w;
            }
        }
    }

    float4* orow = reinterpret_cast<float4*>(out + (size_t)node * OUT_DIM);
#pragma unroll
    for (int j4 = 0; j4 < OUT_DIM / 4; j4++)
        orow[j4] = make_float4(acc[j4 * 4 + 0], acc[j4 * 4 + 1],
                               acc[j4 * 4 + 2], acc[j4 * 4 + 3]);
}

// ---------------- launch ----------------------------------------------------
extern "C" void kernel_launch(void* const* d_in, const int* in_sizes, int n_in,
                              void* d_out, int out_size) {
    const float* x     = (const float*)d_in[0];
    const int*   ei    = (const int*)d_in[1];
    const float* emb_w = (const float*)d_in[2];
    const float* emb_b = (const float*)d_in[3];
    const float* ro_w  = (const float*)d_in[4];
    const float* ro_b  = (const float*)d_in[5];
    float* out = (float*)d_out;

    const int T = 256;
    int blk_node = (N_NODES + T - 1) / T;               // 391
    int blk_edge = (N_EDGES + T - 1) / T;               // 6250
    int blk_gath = (N_NODES * 16 + T - 1) / T;          // 6250

    k_init<<<blk_node, T>>>();
    k_embed<<<blk_node, T>>>(x, emb_w, emb_b);
    k_deg<<<blk_edge, T>>>(ei);
    k_dinv<<<blk_node, T>>>();
    k_scan_block<<<NBLK, 256>>>();
    k_scan_top<<<1, 512>>>();
    k_scan_add<<<NBLK, 256>>>();
    k_fill<<<blk_edge, T>>>(ei);

    float* bufs[2] = {nullptr, nullptr};
    // iter 0: A->B, 1: B->A, 2: A->B, 3: B->A   (final result in g_hA)
    for (int it = 0; it < 4; it++) {
        // resolve device symbol addresses are not needed: pass via kernel args
        // using the globals directly inside the kernel would prevent ping-pong,
        // so we get their addresses with cudaGetSymbolAddress-free trick:
        // instead, launch with explicit pointers obtained below.
        (void)bufs;
    }

    // Obtain device pointers to the ping-pong buffers (host-side, graph-safe).
    static float* p_hA = nullptr;
    static float* p_hB = nullptr;
    if (!p_hA) {
        cudaGetSymbolAddress((void**)&p_hA, g_hA);
        cudaGetSymbolAddress((void**)&p_hB, g_hB);
    }

    k_gather<<<blk_gath, T>>>(p_hA, p_hB);
    k_gather<<<blk_gath, T>>>(p_hB, p_hA);
    k_gather<<<blk_gath, T>>>(p_hA, p_hB);
    k_gather<<<blk_gath, T>>>(p_hB, p_hA);

    k_readout<<<blk_node, T>>>(ro_w, ro_b, out);
    (void)in_sizes; (void)n_in; (void)out_size;
}

// round 4
// speedup vs baseline: 1.7258x; 1.0003x over previous
#include <cuda_runtime.h>
#include <cuda_fp16.h>

#define N_NODES 100000
#define N_EDGES 1600000
#define IN_DIM  128
#define HID     64
#define OUT_DIM 64
#define EPS     0.1f
#define NBLK    ((N_NODES + 255) / 256)   // 391 scan blocks

// ---------------- scratch (static device globals; no runtime alloc) --------
__device__ float  g_hA[N_NODES * HID];    // fp32 node features (ping)
__device__ float  g_hB[N_NODES * HID];    // fp32 node features (pong)
__device__ __half g_hHA[N_NODES * HID];   // fp16 mirror (ping)
__device__ __half g_hHB[N_NODES * HID];   // fp16 mirror (pong)
__device__ int    g_cnt[N_NODES];         // in-degree
__device__ int    g_off[N_NODES];         // CSR row offsets
__device__ int    g_fill[N_NODES];        // fill cursors
__device__ int    g_bsum[NBLK];
__device__ int    g_bpre[NBLK];
__device__ float  g_dinv[N_NODES];        // (deg+2)^{-1/2}
__device__ int2   g_csr[N_EDGES];         // {src, norm-as-int} grouped by dst

// ---------------- init ------------------------------------------------------
__global__ void k_init() {
    int i = blockIdx.x * blockDim.x + threadIdx.x;
    if (i < N_NODES) { g_cnt[i] = 0; g_fill[i] = 0; }
}

// ---------------- embed: hA = x @ emb_w + emb_b (writes fp32 + fp16) --------
__global__ void __launch_bounds__(256) k_embed(const float* __restrict__ x,
                                               const float* __restrict__ w,
                                               const float* __restrict__ b) {
    __shared__ float Ws[IN_DIM * HID];   // 32 KB
    __shared__ float Bs[HID];
    for (int i = threadIdx.x; i < IN_DIM * HID / 4; i += blockDim.x)
        reinterpret_cast<float4*>(Ws)[i] = reinterpret_cast<const float4*>(w)[i];
    if (threadIdx.x < HID) Bs[threadIdx.x] = b[threadIdx.x];
    __syncthreads();

    int node = blockIdx.x * blockDim.x + threadIdx.x;
    if (node >= N_NODES) return;

    float acc[HID];
#pragma unroll
    for (int j = 0; j < HID; j++) acc[j] = Bs[j];

    const float4* xr = reinterpret_cast<const float4*>(x + (size_t)node * IN_DIM);
#pragma unroll 4
    for (int k4 = 0; k4 < IN_DIM / 4; k4++) {
        float4 xv = xr[k4];
        float xk[4] = {xv.x, xv.y, xv.z, xv.w};
#pragma unroll
        for (int kk = 0; kk < 4; kk++) {
            const float4* wrow = reinterpret_cast<const float4*>(Ws + (k4 * 4 + kk) * HID);
#pragma unroll
            for (int j4 = 0; j4 < HID / 4; j4++) {
                float4 wv = wrow[j4];
                acc[j4 * 4 + 0] += xk[kk] * wv.x;
                acc[j4 * 4 + 1] += xk[kk] * wv.y;
                acc[j4 * 4 + 2] += xk[kk] * wv.z;
                acc[j4 * 4 + 3] += xk[kk] * wv.w;
            }
        }
    }

    float4* hout = reinterpret_cast<float4*>(g_hA + (size_t)node * HID);
#pragma unroll
    for (int j4 = 0; j4 < HID / 4; j4++)
        hout[j4] = make_float4(acc[j4 * 4 + 0], acc[j4 * 4 + 1],
                               acc[j4 * 4 + 2], acc[j4 * 4 + 3]);

    half2* hh = reinterpret_cast<half2*>(g_hHA + (size_t)node * HID);
#pragma unroll
    for (int j2 = 0; j2 < HID / 2; j2++)
        hh[j2] = __floats2half2_rn(acc[j2 * 2], acc[j2 * 2 + 1]);
}

// ---------------- degree count ----------------------------------------------
__global__ void k_deg(const int* __restrict__ ei) {
    int e = blockIdx.x * blockDim.x + threadIdx.x;
    if (e >= N_EDGES) return;
    atomicAdd(&g_cnt[ei[N_EDGES + e]], 1);
}

// ---------------- scan phase 1 (also computes dinv) -------------------------
__global__ void k_scan_block() {
    __shared__ int s[256];
    int i = blockIdx.x * 256 + threadIdx.x;
    int v = (i < N_NODES) ? g_cnt[i] : 0;
    if (i < N_NODES) g_dinv[i] = rsqrtf((float)v + 2.0f);
    s[threadIdx.x] = v;
    __syncthreads();
#pragma unroll
    for (int d = 1; d < 256; d <<= 1) {
        int t = (threadIdx.x >= d) ? s[threadIdx.x - d] : 0;
        __syncthreads();
        s[threadIdx.x] += t;
        __syncthreads();
    }
    if (i < N_NODES) g_off[i] = s[threadIdx.x] - v;   // exclusive within block
    if (threadIdx.x == 255) g_bsum[blockIdx.x] = s[255];
}

__global__ void k_scan_top() {
    __shared__ int s[512];
    int tid = threadIdx.x;
    int v = (tid < NBLK) ? g_bsum[tid] : 0;
    s[tid] = v;
    __syncthreads();
#pragma unroll
    for (int d = 1; d < 512; d <<= 1) {
        int t = (tid >= d) ? s[tid - d] : 0;
        __syncthreads();
        s[tid] += t;
        __syncthreads();
    }
    if (tid < NBLK) g_bpre[tid] = s[tid] - v;         // exclusive
}

__global__ void k_scan_add() {
    int i = blockIdx.x * 256 + threadIdx.x;
    if (i < N_NODES) g_off[i] += g_bpre[blockIdx.x];
}

// ---------------- fill CSR ---------------------------------------------------
__global__ void k_fill(const int* __restrict__ ei) {
    int e = blockIdx.x * blockDim.x + threadIdx.x;
    if (e >= N_EDGES) return;
    int src = ei[e];
    int dst = ei[N_EDGES + e];
    int pos = g_off[dst] + atomicAdd(&g_fill[dst], 1);
    g_csr[pos] = make_int2(src, __float_as_int(g_dinv[src] * g_dinv[dst]));
}

// ---------------- gather SpMM + fused update --------------------------------
// 8 threads per node; each thread owns 8 columns (16 B fp16 per edge load).
// hout = hin - EPS*(sum_e norm_e * hin_h[src_e] + 2*dinv^2 * hin)
__global__ void __launch_bounds__(256) k_gather(const float* __restrict__ hin,
                                                const __half* __restrict__ hin_h,
                                                float* __restrict__ hout,
                                                __half* __restrict__ hout_h) {
    int t = blockIdx.x * blockDim.x + threadIdx.x;
    int node = t >> 3;
    int c = (t & 7) << 3;          // column base: 8 halves = 16 B
    if (node >= N_NODES) return;

    int beg = g_off[node];
    int end = beg + g_cnt[node];

    float acc[8];
#pragma unroll
    for (int j = 0; j < 8; j++) acc[j] = 0.f;

#define EDGE_STEP(E)                                                            \
    {                                                                           \
        int2 r = g_csr[E];                                                      \
        float wgt = __int_as_float(r.y);                                        \
        uint4 v = *reinterpret_cast<const uint4*>(hin_h + (size_t)r.x * HID + c); \
        float2 f0 = __half22float2(*reinterpret_cast<half2*>(&v.x));            \
        float2 f1 = __half22float2(*reinterpret_cast<half2*>(&v.y));            \
        float2 f2 = __half22float2(*reinterpret_cast<half2*>(&v.z));            \
        float2 f3 = __half22float2(*reinterpret_cast<half2*>(&v.w));            \
        acc[0] += wgt * f0.x; acc[1] += wgt * f0.y;                             \
        acc[2] += wgt * f1.x; acc[3] += wgt * f1.y;                             \
        acc[4] += wgt * f2.x; acc[5] += wgt * f2.y;                             \
        acc[6] += wgt * f3.x; acc[7] += wgt * f3.y;                             \
    }

    int e = beg;
    for (; e + 3 < end; e += 4) {       // 4-deep for MLP
        EDGE_STEP(e);
        EDGE_STEP(e + 1);
        EDGE_STEP(e + 2);
        EDGE_STEP(e + 3);
    }
    for (; e < end; e++) EDGE_STEP(e);
#undef EDGE_STEP

    float di = g_dinv[node];
    float sw = 2.0f * di * di;
    const float4* hvp = reinterpret_cast<const float4*>(hin + (size_t)node * HID + c);
    float4 h0 = hvp[0];
    float4 h1 = hvp[1];
    float o[8];
    o[0] = h0.x - EPS * (acc[0] + sw * h0.x);
    o[1] = h0.y - EPS * (acc[1] + sw * h0.y);
    o[2] = h0.z - EPS * (acc[2] + sw * h0.z);
    o[3] = h0.w - EPS * (acc[3] + sw * h0.w);
    o[4] = h1.x - EPS * (acc[4] + sw * h1.x);
    o[5] = h1.y - EPS * (acc[5] + sw * h1.y);
    o[6] = h1.z - EPS * (acc[6] + sw * h1.z);
    o[7] = h1.w - EPS * (acc[7] + sw * h1.w);

    float4* op = reinterpret_cast<float4*>(hout + (size_t)node * HID + c);
    op[0] = make_float4(o[0], o[1], o[2], o[3]);
    op[1] = make_float4(o[4], o[5], o[6], o[7]);

    uint4 hv;
    *reinterpret_cast<half2*>(&hv.x) = __floats2half2_rn(o[0], o[1]);
    *reinterpret_cast<half2*>(&hv.y) = __floats2half2_rn(o[2], o[3]);
    *reinterpret_cast<half2*>(&hv.z) = __floats2half2_rn(o[4], o[5]);
    *reinterpret_cast<half2*>(&hv.w) = __floats2half2_rn(o[6], o[7]);
    *reinterpret_cast<uint4*>(hout_h + (size_t)node * HID + c) = hv;
}

// ---------------- readout: out = tanh(hA) @ ro_w + ro_b ---------------------
__global__ void __launch_bounds__(256) k_readout(const float* __restrict__ w,
                                                 const float* __restrict__ b,
                                                 float* __restrict__ out) {
    __shared__ float Ws[HID * OUT_DIM];  // 16 KB
    __shared__ float Bs[OUT_DIM];
    for (int i = threadIdx.x; i < HID * OUT_DIM / 4; i += blockDim.x)
        reinterpret_cast<float4*>(Ws)[i] = reinterpret_cast<const float4*>(w)[i];
    if (threadIdx.x < OUT_DIM) Bs[threadIdx.x] = b[threadIdx.x];
    __syncthreads();

    int node = blockIdx.x * blockDim.x + threadIdx.x;
    if (node >= N_NODES) return;

    float acc[OUT_DIM];
#pragma unroll
    for (int j = 0; j < OUT_DIM; j++) acc[j] = Bs[j];

    const float4* hr = reinterpret_cast<const float4*>(g_hA + (size_t)node * HID);
#pragma unroll 4
    for (int k4 = 0; k4 < HID / 4; k4++) {
        float4 hv = hr[k4];
        float hk[4] = {tanhf(hv.x), tanhf(hv.y), tanhf(hv.z), tanhf(hv.w)};
#pragma unroll
        for (int kk = 0; kk < 4; kk++) {
            const float4* wrow = reinterpret_cast<const float4*>(Ws + (k4 * 4 + kk) * OUT_DIM);
#pragma unroll
            for (int j4 = 0; j4 < OUT_DIM / 4; j4++) {
                float4 wv = wrow[j4];
                acc[j4 * 4 + 0] += hk[kk] * wv.x;
                acc[j4 * 4 + 1] += hk[kk] * wv.y;
                acc[j4 * 4 + 2] += hk[kk] * wv.z;
                acc[j4 * 4 + 3] += hk[kk] * wv.w;
            }
        }
    }

    float4* orow = reinterpret_cast<float4*>(out + (size_t)node * OUT_DIM);
#pragma unroll
    for (int j4 = 0; j4 < OUT_DIM / 4; j4++)
        orow[j4] = make_float4(acc[j4 * 4 + 0], acc[j4 * 4 + 1],
                               acc[j4 * 4 + 2], acc[j4 * 4 + 3]);
}

// ---------------- launch ----------------------------------------------------
extern "C" void kernel_launch(void* const* d_in, const int* in_sizes, int n_in,
                              void* d_out, int out_size) {
    const float* x     = (const float*)d_in[0];
    const int*   ei    = (const int*)d_in[1];
    const float* emb_w = (const float*)d_in[2];
    const float* emb_b = (const float*)d_in[3];
    const float* ro_w  = (const float*)d_in[4];
    const float* ro_b  = (const float*)d_in[5];
    float* out = (float*)d_out;

    const int T = 256;
    int blk_node = (N_NODES + T - 1) / T;               // 391
    int blk_edge = (N_EDGES + T - 1) / T;               // 6250
    int blk_gath = (N_NODES * 8 + T - 1) / T;           // 3125

    static float*  pA = nullptr;
    static float*  pB = nullptr;
    static __half* pHA = nullptr;
    static __half* pHB = nullptr;
    if (!pA) {
        cudaGetSymbolAddress((void**)&pA, g_hA);
        cudaGetSymbolAddress((void**)&pB, g_hB);
        cudaGetSymbolAddress((void**)&pHA, g_hHA);
        cudaGetSymbolAddress((void**)&pHB, g_hHB);
    }

    k_init<<<blk_node, T>>>();
    k_embed<<<blk_node, T>>>(x, emb_w, emb_b);
    k_deg<<<blk_edge, T>>>(ei);
    k_scan_block<<<NBLK, 256>>>();
    k_scan_top<<<1, 512>>>();
    k_scan_add<<<NBLK, 256>>>();
    k_fill<<<blk_edge, T>>>(ei);

    // ping-pong: A->B, B->A, A->B, B->A (final fp32 result in g_hA)
    k_gather<<<blk_gath, T>>>(pA, pHA, pB, pHB);
    k_gather<<<blk_gath, T>>>(pB, pHB, pA, pHA);
    k_gather<<<blk_gath, T>>>(pA, pHA, pB, pHB);
    k_gather<<<blk_gath, T>>>(pB, pHB, pA, pHA);

    k_readout<<<blk_node, T>>>(ro_w, ro_b, out);
    (void)in_sizes; (void)n_in; (void)out_size;
}